// round 2
// baseline (speedup 1.0000x reference)
#include <cuda_runtime.h>

#define EPSF 1e-6f
#define S 32
#define C 3
#define K 4          // tiles (batches) per warp
#define TILE (S * S) // 1024

// Precomputed Thomas factorizations.
// For each element: (invd = 1/denom, w = cs*invd).  Note c_star = -w, so the
// backward sweep reuses w:  x_i = d_i + w_i * x_{i+1}.
// Layout: [timeIdx][c][pos_i][row_r]  -> warp (lane=r) loads 32 consecutive float2.
__device__ float2 g_xcoef[6 * C * TILE];
__device__ float2 g_ycoef[5 * C * TILE];

// ---------------------------------------------------------------------------
// Precompute kernel: one thread per (timeIdx, c, row). 11*3*32 = 1056 threads.
// ---------------------------------------------------------------------------
__global__ void precompute_kernel(const float* __restrict__ ab,
                                  const float* __restrict__ bb,
                                  const float* __restrict__ atc,
                                  const float* __restrict__ btc) {
    int tid = blockIdx.x * blockDim.x + threadIdx.x;
    if (tid >= 11 * C * S) return;
    int j   = tid / (C * S);
    int rem = tid % (C * S);
    int c   = rem / S;
    int r   = rem % S;

    float t, fac;
    const float* bp;
    const float* tp;
    int stride;
    float2* out;
    if (j < 6) {                       // x-direction, t = j*DT, dt = DT/2
        t   = (float)(j * 0.1);
        fac = 0.05f;
        bp  = ab + (c * S + r) * S;    // alpha[c][r][i], i contiguous
        tp  = atc + (c * S + r) * S;
        stride = 1;
        out = g_xcoef + (j * C + c) * TILE;
    } else {                           // y-direction, t = DT/2 + jy*DT, dt = DT
        int jy = j - 6;
        t   = (float)(0.05 + jy * 0.1);
        fac = 0.1f;
        bp  = bb + c * TILE + r;       // beta[c][i][r], i strided by 32
        tp  = btc + c * TILE + r;
        stride = S;
        out = g_ycoef + (jy * C + c) * TILE;
    }

    float coef[S];
#pragma unroll
    for (int i = 0; i < S; ++i)
        coef[i] = fmaxf(bp[i * stride] + t * tp[i * stride], EPSF);

    // replicate-pad 3-tap mean, scaled by dt/dh^2
    float cs[S];
    cs[0] = (coef[0] + coef[0] + coef[1]) / 3.0f * fac;
#pragma unroll
    for (int i = 1; i < S - 1; ++i)
        cs[i] = (coef[i - 1] + coef[i] + coef[i + 1]) / 3.0f * fac;
    cs[S - 1] = (coef[S - 2] + coef[S - 1] + coef[S - 1]) / 3.0f * fac;

    // Thomas factorization: a_i = -cs_i (a_0 = 0), c_i = -cs_i,
    // b = 1+2cs (endpoints 1+cs). denom_i = b_i - a_i*cstar_{i-1} + EPS,
    // cstar_i = -cs_i/denom_i = -w_i.
    float wprev = 0.0f;
#pragma unroll
    for (int i = 0; i < S; ++i) {
        float b = 1.0f + 2.0f * cs[i];
        if (i == 0)     b = 1.0f + cs[0];
        if (i == S - 1) b = 1.0f + cs[S - 1];
        float denom = b - cs[i] * wprev + EPSF;
        float invd  = 1.0f / denom;
        float w     = cs[i] * invd;
        out[i * S + r] = make_float2(invd, w);
        wprev = w;
    }
}

// ---------------------------------------------------------------------------
// Main fused ADI kernel: one warp per CTA, K=4 tiles per warp.
// Registers: v[k][i] holds row `lane` of tile k (current solve direction).
// ---------------------------------------------------------------------------
__global__ __launch_bounds__(32)
void adi_kernel(const float* __restrict__ uin, float* __restrict__ uout) {
    __shared__ float sm[S * 33];
    const int lane = threadIdx.x;
    const int wid  = blockIdx.x;
    const int c    = wid % C;
    const int bg   = wid / C;
    const int base0 = (bg * K) * C * TILE + c * TILE;  // tile k at base0 + k*C*TILE

    float v[K][S];
    float warr[S];

    // ---- load: gmem (coalesced) -> smem -> regs (row layout: lane = h) ----
#pragma unroll
    for (int k = 0; k < K; ++k) {
        const int tb = base0 + k * C * TILE;
        __syncwarp();
#pragma unroll
        for (int r = 0; r < S; ++r)
            sm[r * 33 + lane] = uin[tb + r * S + lane];
        __syncwarp();
#pragma unroll
        for (int i = 0; i < S; ++i)
            v[k][i] = sm[lane * 33 + i];
    }
    __syncwarp();

    // ---- solve: forward then backward Thomas substitution, all K tiles ----
    auto solve = [&](const float2* __restrict__ cf) {
        float dprev[K];
#pragma unroll
        for (int k = 0; k < K; ++k) dprev[k] = 0.0f;
#pragma unroll
        for (int i = 0; i < S; ++i) {
            float2 iw = __ldg(&cf[i * S + lane]);
            warr[i] = iw.y;
#pragma unroll
            for (int k = 0; k < K; ++k) {
                float tt = v[k][i] * iw.x;        // independent of chain
                tt = fmaf(iw.y, dprev[k], tt);    // 4-cycle chain, K-way ILP
                v[k][i] = tt;
                dprev[k] = tt;
            }
        }
#pragma unroll
        for (int i = S - 2; i >= 0; --i) {
#pragma unroll
            for (int k = 0; k < K; ++k)
                v[k][i] = fmaf(warr[i], v[k][i + 1], v[k][i]);
        }
    };

    // ---- 32x32 register transpose via padded smem (conflict-free) ----
    auto transpose = [&]() {
#pragma unroll
        for (int k = 0; k < K; ++k) {
            __syncwarp();
#pragma unroll
            for (int i = 0; i < S; ++i) sm[lane * 33 + i] = v[k][i];
            __syncwarp();
#pragma unroll
            for (int i = 0; i < S; ++i) v[k][i] = sm[i * 33 + lane];
        }
        __syncwarp();
    };

    const float2* xc = g_xcoef + c * TILE;   // + j*C*TILE per time index
    const float2* yc = g_ycoef + c * TILE;

    // substep sequence: X0 | [T Y_it T X_{it+1} (X_{it+1})] for it=0..4
    solve(xc);
#pragma unroll 1
    for (int it = 0; it < 5; ++it) {
        transpose();
        solve(yc + it * C * TILE);
        transpose();
        const float2* cfx = xc + (it + 1) * C * TILE;
        const int reps = (it < 4) ? 2 : 1;   // same t twice across iter boundary
#pragma unroll 1
        for (int rr = 0; rr < reps; ++rr) solve(cfx);
    }

    // ---- store: regs -> smem -> gmem (coalesced) ----
#pragma unroll
    for (int k = 0; k < K; ++k) {
        const int tb = base0 + k * C * TILE;
        __syncwarp();
#pragma unroll
        for (int i = 0; i < S; ++i) sm[lane * 33 + i] = v[k][i];
        __syncwarp();
#pragma unroll
        for (int r = 0; r < S; ++r)
            uout[tb + r * S + lane] = sm[r * 33 + lane];
    }
}

// ---------------------------------------------------------------------------
extern "C" void kernel_launch(void* const* d_in, const int* in_sizes, int n_in,
                              void* d_out, int out_size) {
    const float* u   = (const float*)d_in[0];
    const float* ab  = (const float*)d_in[1];
    const float* bb  = (const float*)d_in[2];
    const float* atc = (const float*)d_in[3];
    const float* btc = (const float*)d_in[4];
    float* out = (float*)d_out;

    const int B = in_sizes[0] / (C * TILE);   // 2048

    precompute_kernel<<<(11 * C * S + 127) / 128, 128>>>(ab, bb, atc, btc);

    const int nwarps = (B / K) * C;           // 1536 single-warp CTAs
    adi_kernel<<<nwarps, 32>>>(u, out);
}